// round 16
// baseline (speedup 1.0000x reference)
#include <cuda_runtime.h>
#include <cuda_fp16.h>
#include <cstdint>
#include <math_constants.h>

// VQ nearest-codebook via two-phase argmin:
//  Pass 1 (coarse): fp16 hh-only mma distance scores -> fp16 gmem (4.19M mma).
//  Pass 2 (select): per-row warp finds max, rescores candidates within a
//  provably safe band (1.0) with exact fp32 dots, gathers outputs.
//   z_e_x: [16,2048,256] f32, embedding: [1024,256] f32
// d_out (f32): z_q_x [N*D] @0, z_q_x_bar @8388608, indices @16777216

#define NTOK   32768
#define DDIM   256
#define KCODE  1024
#define BM     128
#define BN     128
#define NSEG   4
#define SEGK   256
#define KS     32
#define NG     16              // 2 tiles * 8 stages
#define PITCHH 40

#define OUT_BAR   8388608
#define OUT_IDX  16777216
#define BAND   1.0f

#define MAT_H   (BM * PITCHH)            // 5120 halves per matrix-stage
// layout: Ah[buf] = buf*MAT_H (2), Bh[buf] = (2+buf)*MAT_H (2)
#define DYN_SMEM (4 * MAT_H * 2)         // 40960 B

__device__ float g_cnorm[KCODE];
__device__ __align__(16) __half g_scores[(size_t)NTOK * KCODE];   // raw hh dots

// ---------------------------------------------------------------------------
__device__ __forceinline__ uint32_t smem_u32(const void* p) {
    uint32_t a;
    asm("{ .reg .u64 t; cvta.to.shared.u64 t, %1; cvt.u32.u64 %0, t; }"
        : "=r"(a) : "l"(p));
    return a;
}
#define LDSM4(r, addr) \
    asm volatile("ldmatrix.sync.aligned.m8n8.x4.shared.b16 {%0,%1,%2,%3}, [%4];" \
        : "=r"((r)[0]), "=r"((r)[1]), "=r"((r)[2]), "=r"((r)[3]) : "r"(addr))

__device__ __forceinline__ void mma_f16(float* c, const uint32_t* a,
                                        uint32_t b0, uint32_t b1) {
    asm volatile(
        "mma.sync.aligned.m16n8k16.row.col.f32.f16.f16.f32 "
        "{%0,%1,%2,%3}, {%4,%5,%6,%7}, {%8,%9}, {%0,%1,%2,%3};"
        : "+f"(c[0]), "+f"(c[1]), "+f"(c[2]), "+f"(c[3])
        : "r"(a[0]), "r"(a[1]), "r"(a[2]), "r"(a[3]), "r"(b0), "r"(b1));
}

__device__ __forceinline__ uint32_t h2u(__half2 v) {
    return *reinterpret_cast<uint32_t*>(&v);
}

// hi-only fp16 conversion of one float4 -> uint2
__device__ __forceinline__ uint2 hi_f4(float4 v) {
    uint2 h;
    h.x = h2u(__floats2half2_rn(v.x, v.y));
    h.y = h2u(__floats2half2_rn(v.z, v.w));
    return h;
}

// ---------------------------------------------------------------------------
__global__ void cnorm_kernel(const float* __restrict__ emb) {
    int warp = (blockIdx.x * blockDim.x + threadIdx.x) >> 5;
    int lane = threadIdx.x & 31;
    if (warp >= KCODE) return;
    const float* row = emb + (size_t)warp * DDIM;
    float s = 0.f;
    #pragma unroll
    for (int k = lane; k < DDIM; k += 32) { float v = row[k]; s += v * v; }
    #pragma unroll
    for (int o = 16; o; o >>= 1) s += __shfl_xor_sync(0xffffffffu, s, o);
    if (lane == 0) g_cnorm[warp] = s;
}

// ---------------------------------------------------------------------------
// Pass 1: coarse hh scores. 256 threads = 8 warps 4(m)x2(n), warp tile 32x64.
// CTA b: rows [(b>>2)*128, +128), codes [(b&3)*256, +256).
// ---------------------------------------------------------------------------
__global__ __launch_bounds__(256, 2)
void coarse_kernel(const float* __restrict__ x,
                   const float* __restrict__ emb) {
    extern __shared__ __half hsm[];

    const int tid = threadIdx.x;
    const int wid = tid >> 5;
    const int L   = tid & 31;
    const int rowBase = (blockIdx.x >> 2) * BM;
    const int segBase = (blockIdx.x & 3) * SEGK;
    const int mbase = (wid >> 1) * 32;
    const int nbase = (wid & 1) * 64;

    const uint32_t SB = smem_u32(hsm);
    const int aRow = (L & 7) + 8 * ((L >> 3) & 1);
    const int aK   = (L >> 4) * 16;
    const uint32_t aBase = (uint32_t)((mbase + aRow) * 80 + aK);
    const uint32_t bBase = (uint32_t)((nbase + aRow) * 80 + aK);

    const int lRow = tid >> 1;
    const int lKh  = (tid & 1) * 16;

    float4 vS[4];

    #define LOAD_A(sidx) do { \
        const int _ko = ((sidx) & 7) * KS + lKh; \
        const float* xp = x + (size_t)(rowBase + lRow) * DDIM + _ko; \
        vS[0] = *(const float4*)(xp);      vS[1] = *(const float4*)(xp + 4); \
        vS[2] = *(const float4*)(xp + 8);  vS[3] = *(const float4*)(xp + 12); \
    } while (0)

    #define LOAD_B(sidx) do { \
        const int _t  = (sidx) >> 3; \
        const int _ko = ((sidx) & 7) * KS + lKh; \
        const float* bp = emb + (size_t)(segBase + _t * BN + lRow) * DDIM + _ko; \
        vS[0] = *(const float4*)(bp);      vS[1] = *(const float4*)(bp + 4); \
        vS[2] = *(const float4*)(bp + 8);  vS[3] = *(const float4*)(bp + 12); \
    } while (0)

    #define STORE_HI(matH) do { \
        const int _hb = lRow * PITCHH + lKh; \
        uint4 _p0, _p1; \
        uint2 _a = hi_f4(vS[0]), _b = hi_f4(vS[1]); \
        uint2 _c = hi_f4(vS[2]), _d = hi_f4(vS[3]); \
        _p0.x = _a.x; _p0.y = _a.y; _p0.z = _b.x; _p0.w = _b.y; \
        _p1.x = _c.x; _p1.y = _c.y; _p1.z = _d.x; _p1.w = _d.y; \
        *(uint4*)&hsm[(matH) + _hb]     = _p0; \
        *(uint4*)&hsm[(matH) + _hb + 8] = _p1; \
    } while (0)

    float acc[2][8][4];
    #pragma unroll
    for (int f = 0; f < 2; ++f)
        #pragma unroll
        for (int n = 0; n < 8; ++n)
            #pragma unroll
            for (int e = 0; e < 4; ++e) acc[f][n][e] = 0.f;

    LOAD_A(0); STORE_HI(0);
    LOAD_B(0); STORE_HI(2 * MAT_H);
    __syncthreads();

    for (int g = 0; g < NG; ++g) {
        const int buf = g & 1;
        const uint32_t AHB = SB + (uint32_t)(buf * MAT_H) * 2;
        const uint32_t BHB = SB + (uint32_t)((2 + buf) * MAT_H) * 2;
        const int ahN = (buf ^ 1) * MAT_H;
        const int bhN = (2 + (buf ^ 1)) * MAT_H;
        const bool pf = (g + 1 < NG);

        if (pf) LOAD_A(g + 1);

        #pragma unroll
        for (int kk = 0; kk < 2; ++kk) {
            const uint32_t kof = (uint32_t)(kk * 32);
            uint32_t ah[2][4], bh[4][4];
            #pragma unroll
            for (int f = 0; f < 2; ++f) LDSM4(ah[f], AHB + aBase + f * 1280 + kof);
            #pragma unroll
            for (int q = 0; q < 4; ++q) LDSM4(bh[q], BHB + bBase + q * 1280 + kof);
            #pragma unroll
            for (int f = 0; f < 2; ++f)
                #pragma unroll
                for (int q = 0; q < 4; ++q) {
                    mma_f16(acc[f][2 * q],     ah[f], bh[q][0], bh[q][2]);
                    mma_f16(acc[f][2 * q + 1], ah[f], bh[q][1], bh[q][3]);
                }
            if (kk == 0) { if (pf) { STORE_HI(ahN); LOAD_B(g + 1); } }
            else         { if (pf) STORE_HI(bhN); }
        }

        // ---- tile end: stream raw hh scores to gmem (half2, row-major) ----
        if ((g & 7) == 7) {
            const int cbT = segBase + (g >> 3) * BN;
            #pragma unroll
            for (int f = 0; f < 2; ++f) {
                const int r = rowBase + mbase + 16 * f + (L >> 2);
                #pragma unroll
                for (int n = 0; n < 8; ++n) {
                    const int c = cbT + nbase + 8 * n + 2 * (L & 3);
                    __half2 p0 = __floats2half2_rn(acc[f][n][0], acc[f][n][1]);
                    __half2 p1 = __floats2half2_rn(acc[f][n][2], acc[f][n][3]);
                    *(__half2*)(g_scores + (size_t)r * KCODE + c) = p0;
                    *(__half2*)(g_scores + (size_t)(r + 8) * KCODE + c) = p1;
                }
            }
            if (g + 1 < NG) {
                #pragma unroll
                for (int f = 0; f < 2; ++f)
                    #pragma unroll
                    for (int n = 0; n < 8; ++n)
                        #pragma unroll
                        for (int e = 0; e < 4; ++e) acc[f][n][e] = 0.f;
            }
        }
        __syncthreads();
    }
}

// ---------------------------------------------------------------------------
// Pass 2: one warp per row. Find coarse max, rescore in-band candidates with
// exact fp32 dot, pick winner (tie -> smaller index), gather outputs.
// ---------------------------------------------------------------------------
__global__ __launch_bounds__(256)
void select_kernel(const float* __restrict__ x,
                   const float* __restrict__ emb,
                   float* __restrict__ out) {
    __shared__ float cn[KCODE];
    const int tid = threadIdx.x;
    const int wid = tid >> 5;
    const int L   = tid & 31;

    #pragma unroll
    for (int i = 0; i < 4; ++i) cn[tid + 256 * i] = g_cnorm[tid + 256 * i];
    __syncthreads();

    const int row = blockIdx.x * 8 + wid;

    // load this lane's 32 coarse scores (codes [32L, 32L+32))
    __half2 hs[16];
    {
        const uint4* sp = (const uint4*)(g_scores + (size_t)row * KCODE + L * 32);
        uint4 u0 = sp[0], u1 = sp[1], u2 = sp[2], u3 = sp[3];
        uint32_t raw[16] = {u0.x,u0.y,u0.z,u0.w, u1.x,u1.y,u1.z,u1.w,
                            u2.x,u2.y,u2.z,u2.w, u3.x,u3.y,u3.z,u3.w};
        #pragma unroll
        for (int i = 0; i < 16; ++i) hs[i] = *reinterpret_cast<__half2*>(&raw[i]);
    }
    float sc[32];
    #pragma unroll
    for (int i = 0; i < 16; ++i) {
        float2 f = __half22float2(hs[i]);
        int c0 = L * 32 + 2 * i;
        sc[2 * i]     = f.x - 0.5f * cn[c0];
        sc[2 * i + 1] = f.y - 0.5f * cn[c0 + 1];
    }

    // warp max of coarse scores
    float m = -CUDART_INF_F;
    #pragma unroll
    for (int j = 0; j < 32; ++j) m = fmaxf(m, sc[j]);
    #pragma unroll
    for (int o = 16; o; o >>= 1) m = fmaxf(m, __shfl_xor_sync(0xffffffffu, m, o));
    const float thr = m - BAND;

    // preload x row (8 floats per lane)
    const float4* xr = (const float4*)(x + (size_t)row * DDIM + L * 8);
    float4 xv0 = xr[0], xv1 = xr[1];

    float bestD = CUDART_INF_F;
    int   bestI = 0x7fffffff;

    #pragma unroll 4
    for (int j = 0; j < 32; ++j) {
        uint32_t mask = __ballot_sync(0xffffffffu, sc[j] >= thr);
        while (mask) {
            int l = __ffs(mask) - 1;
            mask &= mask - 1;
            int code = l * 32 + j;
            // exact fp32 warp dot
            const float4* cr = (const float4*)(emb + (size_t)code * DDIM + L * 8);
            float4 cv0 = cr[0], cv1 = cr[1];
            float p = xv0.x * cv0.x + xv0.y * cv0.y + xv0.z * cv0.z + xv0.w * cv0.w
                    + xv1.x * cv1.x + xv1.y * cv1.y + xv1.z * cv1.z + xv1.w * cv1.w;
            #pragma unroll
            for (int o = 16; o; o >>= 1) p += __shfl_xor_sync(0xffffffffu, p, o);
            float d = fmaf(-2.f, p, cn[code]);
            if (d < bestD || (d == bestD && code < bestI)) { bestD = d; bestI = code; }
        }
    }

    if (L == 0) out[OUT_IDX + row] = (float)bestI;

    // gather winning code row -> z_q_x and z_q_x_bar
    const float4* w = (const float4*)(emb + (size_t)bestI * DDIM);
    float4* o4 = (float4*)out;
    const size_t ro = (size_t)row * 64;
    float4 v0 = w[L], v1 = w[L + 32];
    o4[ro + L] = v0;
    o4[ro + L + 32] = v1;
    o4[ro + (OUT_BAR / 4) + L] = v0;
    o4[ro + (OUT_BAR / 4) + L + 32] = v1;
}

// ---------------------------------------------------------------------------
extern "C" void kernel_launch(void* const* d_in, const int* in_sizes, int n_in,
                              void* d_out, int out_size) {
    const float* x   = (const float*)d_in[0];
    const float* emb = (const float*)d_in[1];
    float* out = (float*)d_out;

    cudaFuncSetAttribute(coarse_kernel, cudaFuncAttributeMaxDynamicSharedMemorySize, DYN_SMEM);

    cnorm_kernel<<<KCODE / 8, 256>>>(emb);
    coarse_kernel<<<(NTOK / BM) * NSEG, 256, DYN_SMEM>>>(x, emb);
    select_kernel<<<NTOK / 8, 256>>>(x, emb, out);
}